// round 15
// baseline (speedup 1.0000x reference)
#include <cuda_runtime.h>
#include <cuda_fp16.h>
#include <cstdint>
#include <cstddef>

// ---------------------------------------------------------------------------
// WL2 graph conv layer — fp16 mma.sync GEMMs + counting-sorted gather conv,
// with two-level stream pipelining:
//   main : prep_w -> prep_x -> gemm_xwn -> conv[0,h) -> final[0,h) -> final[h,n)
//   side : sort chain ----------------------^-> conv[h,n) ----------^
// R15 = R14 (300us) + split conv/final halves overlapped (the ONLY change).
// ---------------------------------------------------------------------------

#define NMAX   200000
#define MEDGE  2000000
#define HPAD   200704              // 196 * 1024 (padded histogram length)
#define NBLK   196                 // scan blocks of 1024
#define MAXELEMS ((size_t)NMAX * 128)

__device__ __half g_xh[MAXELEMS];        // fp16 copy of X
__device__ __half g_xwnh[MAXELEMS];      // fp16 neighbor projection
__device__ float  g_conv[MAXELEMS];      // conv rows (written once, no atomics)
__device__ __half g_wth[3 * 128 * 128];  // W^T (K-major), fp16

__device__ int  g_hist[HPAD];
__device__ int  g_rowscan[HPAD];
__device__ int  g_bsum[NBLK];
__device__ int  g_bsumoff[NBLK];
__device__ int  g_rowstart[NMAX + 1];
__device__ int  g_cursor[NMAX];
__device__ int2 g_sab[MEDGE];            // sorted (ref_a, ref_b) pairs

// ---------------- helpers ----------------
__device__ __forceinline__ uint32_t smem_u32(const void* p) {
    uint32_t a;
    asm("{ .reg .u64 t; cvta.to.shared.u64 t, %1; cvt.u32.u64 %0, t; }"
        : "=r"(a) : "l"(p));
    return a;
}

__device__ __forceinline__ void cp_async16(uint32_t dst, const void* src) {
    asm volatile("cp.async.ca.shared.global [%0], [%1], 16;"
                 :: "r"(dst), "l"(src) : "memory");
}
__device__ __forceinline__ void cp_commit() {
    asm volatile("cp.async.commit_group;" ::: "memory");
}
__device__ __forceinline__ void cp_wait1() {
    asm volatile("cp.async.wait_group 1;" ::: "memory");
}

// fp16 mma with fp32 accumulators: D = A(16x16,row) * B(16x8,col) + D
__device__ __forceinline__ void mma_f16(float* c,
                                        uint32_t a0, uint32_t a1, uint32_t a2, uint32_t a3,
                                        uint32_t b0, uint32_t b1) {
    asm volatile(
        "mma.sync.aligned.m16n8k16.row.col.f32.f16.f16.f32 "
        "{%0,%1,%2,%3}, {%4,%5,%6,%7}, {%8,%9}, {%0,%1,%2,%3};"
        : "+f"(c[0]), "+f"(c[1]), "+f"(c[2]), "+f"(c[3])
        : "r"(a0), "r"(a1), "r"(a2), "r"(a3), "r"(b0), "r"(b1));
}

// smem tile geometry: rows of 128 halves padded to 136 (272 B).
#define HPITCH_B    272                   // bytes per padded row
#define TILE_BYTES  (128 * HPITCH_B)      // 34816 B per 128-row tile
#define FTILE_BYTES (64 * HPITCH_B)       // 17408 B per 64-row A tile

// ---------------------------------------------------------------------------
// Phase 0a: W^T -> fp16
// ---------------------------------------------------------------------------
__global__ void prep_w_kernel(const float* __restrict__ Wl,
                              const float* __restrict__ Wf,
                              const float* __restrict__ Wn) {
    const float* src = (blockIdx.x == 0) ? Wl : ((blockIdx.x == 1) ? Wf : Wn);
    __half* dst = g_wth + blockIdx.x * 16384;
    for (int i = threadIdx.x; i < 16384; i += blockDim.x) {
        int n = i >> 7, k = i & 127;
        dst[i] = __float2half_rn(src[k * 128 + n]);   // [n][k]
    }
}

// ---------------------------------------------------------------------------
// Phase 0b: X -> fp16
// ---------------------------------------------------------------------------
__global__ void prep_x_kernel(const float* __restrict__ X, int total4) {
    const int i = blockIdx.x * 256 + threadIdx.x;
    if (i >= total4) return;
    const float4 v = reinterpret_cast<const float4*>(X)[i];
    const __half2 h0 = __floats2half2_rn(v.x, v.y);
    const __half2 h1 = __floats2half2_rn(v.z, v.w);
    uint2 o;
    o.x = *reinterpret_cast<const uint32_t*>(&h0);
    o.y = *reinterpret_cast<const uint32_t*>(&h1);
    reinterpret_cast<uint2*>(g_xh)[i] = o;
}

// ---------------------------------------------------------------------------
// Phase 1 (side stream): counting sort of edges by backref
// ---------------------------------------------------------------------------
__global__ void hist_zero_kernel() {
    int i = blockIdx.x * 256 + threadIdx.x;
    if (i < HPAD) g_hist[i] = 0;
}

__global__ void hist_kernel(const int* __restrict__ br, int m) {
    for (int e = blockIdx.x * 256 + threadIdx.x; e < m; e += gridDim.x * 256)
        atomicAdd(&g_hist[__ldg(br + e)], 1);
}

__global__ void scan1_kernel() {
    __shared__ int wsum[8];
    const int t = threadIdx.x;
    const int base = blockIdx.x * 1024 + t * 4;
    const int4 v = *reinterpret_cast<const int4*>(g_hist + base);
    const int s1 = v.x + v.y, s2 = s1 + v.z, s3 = s2 + v.w;
    const int lane = t & 31, w = t >> 5;
    int x = s3;
#pragma unroll
    for (int d = 1; d < 32; d <<= 1) {
        int y = __shfl_up_sync(0xffffffffu, x, d);
        if (lane >= d) x += y;
    }
    if (lane == 31) wsum[w] = x;
    __syncthreads();
    if (t < 8) {
        int v2 = wsum[t];
#pragma unroll
        for (int d = 1; d < 8; d <<= 1) {
            int y = __shfl_up_sync(0xffu, v2, d);
            if (t >= d) v2 += y;
        }
        wsum[t] = v2;
    }
    __syncthreads();
    const int woff = w ? wsum[w - 1] : 0;
    const int excl = woff + x - s3;
    int4 o;
    o.x = excl; o.y = excl + v.x; o.z = excl + s1; o.w = excl + s2;
    *reinterpret_cast<int4*>(g_rowscan + base) = o;
    if (t == 255) g_bsum[blockIdx.x] = wsum[7];
}

__global__ void scan2_kernel() {
    __shared__ int wsum[8];
    const int t = threadIdx.x;
    const int v = (t < NBLK) ? g_bsum[t] : 0;
    const int lane = t & 31, w = t >> 5;
    int x = v;
#pragma unroll
    for (int d = 1; d < 32; d <<= 1) {
        int y = __shfl_up_sync(0xffffffffu, x, d);
        if (lane >= d) x += y;
    }
    if (lane == 31) wsum[w] = x;
    __syncthreads();
    if (t < 8) {
        int v2 = wsum[t];
#pragma unroll
        for (int d = 1; d < 8; d <<= 1) {
            int y = __shfl_up_sync(0xffu, v2, d);
            if (t >= d) v2 += y;
        }
        wsum[t] = v2;
    }
    __syncthreads();
    const int woff = w ? wsum[w - 1] : 0;
    if (t < NBLK) g_bsumoff[t] = woff + x - v;
}

__global__ void scan3_kernel(int n, int m) {
    const int i = blockIdx.x * 256 + threadIdx.x;
    if (i < n) {
        const int val = g_rowscan[i] + g_bsumoff[i >> 10];
        g_rowstart[i] = val;
        g_cursor[i] = val;
    }
    if (i == 0) g_rowstart[n] = m;
}

__global__ void scatter_kernel(const int* __restrict__ ra,
                               const int* __restrict__ rb,
                               const int* __restrict__ br, int m) {
    const int e = blockIdx.x * 256 + threadIdx.x;
    if (e >= m) return;
    const int c = __ldg(br + e);
    const int p = atomicAdd(&g_cursor[c], 1);
    g_sab[p] = make_int2(__ldg(ra + e), __ldg(rb + e));
}

// ---------------------------------------------------------------------------
// B-tile loader: g_wth [n][k] fp16 -> smem padded rows. 512 threads.
// ---------------------------------------------------------------------------
__device__ __forceinline__ void load_b_tile(char* dst, const __half* __restrict__ Wt,
                                            int tid) {
    for (int i = tid; i < 2048; i += 512) {
        const int r = i >> 4, c = i & 15;
        const uint4 v = *reinterpret_cast<const uint4*>(Wt + r * 128 + c * 8);
        *reinterpret_cast<uint4*>(dst + r * HPITCH_B + c * 16) = v;
    }
}

// ---------------------------------------------------------------------------
// Phase 2: XW_n = X @ W_n, persistent; 128-row chunks, double-buffered A.
// 16 warps: m-group = wid&7 (16 rows), n-group = wid>>3 (64 cols, 8 nt).
// ---------------------------------------------------------------------------
#define XB_OFF   0
#define XA0_OFF  TILE_BYTES
#define XA1_OFF  (2 * TILE_BYTES)
#define SMEM_X   (3 * TILE_BYTES)      // 104448 B

__global__ __launch_bounds__(512, 1)
void gemm_xwn_kernel(int nrows) {
    extern __shared__ __align__(16) char smem[];
    const uint32_t sb = smem_u32(smem);

    const int tid = threadIdx.x;
    const int ntiles = (nrows + 127) / 128;
    const int stride = gridDim.x;
    const uint32_t aoff[2] = { XA0_OFF, XA1_OFF };

    load_b_tile(smem + XB_OFF, g_wth + 2 * 16384, tid);

    int tile0 = blockIdx.x;
    if (tile0 < ntiles) {
#pragma unroll
        for (int j = 0; j < 4; j++) {
            const int i = tid + j * 512;
            const int r = i >> 4, c = i & 15;
            const int gr = tile0 * 128 + r;
            if (gr < nrows)
                cp_async16(sb + aoff[0] + (uint32_t)(r * HPITCH_B + c * 16),
                           g_xh + (size_t)gr * 128 + c * 8);
        }
    }
    cp_commit();

    const int wid = tid >> 5, lane = tid & 31;
    const int g = lane >> 2, t = lane & 3;
    const int m_base = (wid & 7) * 16;
    const int n_base = (wid >> 3) * 64;

    int buf = 0;
    for (int tile = tile0; tile < ntiles; tile += stride, buf ^= 1) {
        const int nxt = tile + stride;
        if (nxt < ntiles) {
#pragma unroll
            for (int j = 0; j < 4; j++) {
                const int i = tid + j * 512;
                const int r = i >> 4, c = i & 15;
                const int gr = nxt * 128 + r;
                if (gr < nrows)
                    cp_async16(sb + aoff[buf ^ 1] + (uint32_t)(r * HPITCH_B + c * 16),
                               g_xh + (size_t)gr * 128 + c * 8);
            }
        }
        cp_commit();
        cp_wait1();
        __syncthreads();

        float acc[8][4];
#pragma unroll
        for (int nt = 0; nt < 8; nt++)
#pragma unroll
            for (int j = 0; j < 4; j++) acc[nt][j] = 0.f;

        const char* ar = smem + aoff[buf] + (m_base + g) * HPITCH_B + 4 * t;
        const char* br = smem + XB_OFF + (n_base + g) * HPITCH_B + 4 * t;

#pragma unroll
        for (int ks = 0; ks < 8; ks++) {
            const int kb = ks * 32;   // 16 halves = 32 bytes per K-step
            const uint32_t a0 = *reinterpret_cast<const uint32_t*>(ar + kb);
            const uint32_t a1 = *reinterpret_cast<const uint32_t*>(ar + 8 * HPITCH_B + kb);
            const uint32_t a2 = *reinterpret_cast<const uint32_t*>(ar + kb + 16);
            const uint32_t a3 = *reinterpret_cast<const uint32_t*>(ar + 8 * HPITCH_B + kb + 16);
#pragma unroll
            for (int nt = 0; nt < 8; nt++) {
                const uint32_t b0 = *reinterpret_cast<const uint32_t*>(br + nt * 8 * HPITCH_B + kb);
                const uint32_t b1 = *reinterpret_cast<const uint32_t*>(br + nt * 8 * HPITCH_B + kb + 16);
                mma_f16(acc[nt], a0, a1, a2, a3, b0, b1);
            }
        }

        const int r0 = tile * 128 + m_base + g;
        const int r1 = r0 + 8;
#pragma unroll
        for (int nt = 0; nt < 8; nt++) {
            const int col = n_base + nt * 8 + 2 * t;
            if (r0 < nrows)
                *reinterpret_cast<__half2*>(g_xwnh + (size_t)r0 * 128 + col) =
                    __floats2half2_rn(acc[nt][0], acc[nt][1]);
            if (r1 < nrows)
                *reinterpret_cast<__half2*>(g_xwnh + (size_t)r1 * 128 + col) =
                    __floats2half2_rn(acc[nt][2], acc[nt][3]);
        }
        __syncthreads();
    }
}

// ---------------------------------------------------------------------------
// Phase 3: conv rows over [r_lo, r_hi). One warp per TWO rows (interleaved
// gathers); register sum, single coalesced store per row.
// ---------------------------------------------------------------------------
__global__ __launch_bounds__(256)
void conv_row_kernel(const float* __restrict__ bn, int r_lo, int r_hi) {
    const int wid = threadIdx.x >> 5, lane = threadIdx.x & 31;
    const int r0 = r_lo + (blockIdx.x * 8 + wid) * 2;
    if (r0 >= r_hi) return;
    const int r1 = (r0 + 1 < r_hi) ? (r0 + 1) : r0;

    const int s0a = g_rowstart[r0];
    const int s0b = g_rowstart[r0 + 1];
    const int s1a = (r1 != r0) ? g_rowstart[r1] : s0a;
    const int s1b = (r1 != r0) ? g_rowstart[r1 + 1] : s0a;

    const float4 bb = __ldg(reinterpret_cast<const float4*>(bn) + lane);

    float a0x = 0.f, a0y = 0.f, a0z = 0.f, a0w = 0.f;
    float a1x = 0.f, a1y = 0.f, a1z = 0.f, a1w = 0.f;

    int i0 = s0a, i1 = s1a;
    while (i0 < s0b && i1 < s1b) {
        const int2 e0 = __ldg(g_sab + i0);
        const int2 e1 = __ldg(g_sab + i1);
        const uint2 pa0 = *reinterpret_cast<const uint2*>(g_xwnh + (size_t)e0.x * 128 + lane * 4);
        const uint2 pb0 = *reinterpret_cast<const uint2*>(g_xwnh + (size_t)e0.y * 128 + lane * 4);
        const uint2 pa1 = *reinterpret_cast<const uint2*>(g_xwnh + (size_t)e1.x * 128 + lane * 4);
        const uint2 pb1 = *reinterpret_cast<const uint2*>(g_xwnh + (size_t)e1.y * 128 + lane * 4);
        {
            const float2 x01 = __half22float2(*reinterpret_cast<const __half2*>(&pa0.x));
            const float2 x23 = __half22float2(*reinterpret_cast<const __half2*>(&pa0.y));
            const float2 y01 = __half22float2(*reinterpret_cast<const __half2*>(&pb0.x));
            const float2 y23 = __half22float2(*reinterpret_cast<const __half2*>(&pb0.y));
            a0x += fmaxf(x01.x + y01.x + bb.x, 0.f);
            a0y += fmaxf(x01.y + y01.y + bb.y, 0.f);
            a0z += fmaxf(x23.x + y23.x + bb.z, 0.f);
            a0w += fmaxf(x23.y + y23.y + bb.w, 0.f);
        }
        {
            const float2 x01 = __half22float2(*reinterpret_cast<const __half2*>(&pa1.x));
            const float2 x23 = __half22float2(*reinterpret_cast<const __half2*>(&pa1.y));
            const float2 y01 = __half22float2(*reinterpret_cast<const __half2*>(&pb1.x));
            const float2 y23 = __half22float2(*reinterpret_cast<const __half2*>(&pb1.y));
            a1x += fmaxf(x01.x + y01.x + bb.x, 0.f);
            a1y += fmaxf(x01.y + y01.y + bb.y, 0.f);
            a1z += fmaxf(x23.x + y23.x + bb.z, 0.f);
            a1w += fmaxf(x23.y + y23.y + bb.w, 0.f);
        }
        i0++; i1++;
    }
    for (; i0 + 2 <= s0b; i0 += 2) {
        const int2 e0 = __ldg(g_sab + i0);
        const int2 e1 = __ldg(g_sab + i0 + 1);
        const uint2 pa0 = *reinterpret_cast<const uint2*>(g_xwnh + (size_t)e0.x * 128 + lane * 4);
        const uint2 pb0 = *reinterpret_cast<const uint2*>(g_xwnh + (size_t)e0.y * 128 + lane * 4);
        const uint2 pa1 = *reinterpret_cast<const uint2*>(g_xwnh + (size_t)e1.x * 128 + lane * 4);
        const uint2 pb1 = *reinterpret_cast<const uint2*>(g_xwnh + (size_t)e1.y * 128 + lane * 4);
        {
            const float2 x01 = __half22float2(*reinterpret_cast<const __half2*>(&pa0.x));
            const float2 x23 = __half22float2(*reinterpret_cast<const __half2*>(&pa0.y));
            const float2 y01 = __half22float2(*reinterpret_cast<const __half2*>(&pb0.x));
            const float2 y23 = __half22float2(*reinterpret_cast<const __half2*>(&pb0.y));
            a0x += fmaxf(x01.x + y01.x + bb.x, 0.f);
            a0y += fmaxf(x01.y + y01.y + bb.y, 0.f);
            a0z += fmaxf(x23.x + y23.x + bb.z, 0.f);
            a0w += fmaxf(x23.y + y23.y + bb.w, 0.f);
        }
        {
            const float2 x01 = __half22float2(*reinterpret_cast<const __half2*>(&pa1.x));
            const float2 x23 = __half22float2(*reinterpret_cast<const __half2*>(&pa1.y));
            const float2 y01 = __half22float2(*reinterpret_cast<const __half2*>(&pb1.x));
            const float2 y23 = __half22float2(*reinterpret_cast<const __half2*>(&pb1.y));
            a0x += fmaxf(x01.x + y01.x + bb.x, 0.f);
            a0y += fmaxf(x01.y + y01.y + bb.y, 0.f);
            a0z += fmaxf(x23.x + y23.x + bb.z, 0.f);
            a0w += fmaxf(x23.y + y23.y + bb.w, 0.f);
        }
    }
    for (; i0 < s0b; i0++) {
        const int2 e0 = __ldg(g_sab + i0);
        const uint2 pa0 = *reinterpret_cast<const uint2*>(g_xwnh + (size_t)e0.x * 128 + lane * 4);
        const uint2 pb0 = *reinterpret_cast<const uint2*>(g_xwnh + (size_t)e0.y * 128 + lane * 4);
        const float2 x01 = __half22float2(*reinterpret_cast<const __half2*>(&pa0.x));
        const float2 x23 = __half22float2(*reinterpret_cast<const __half2*>(&pa0.y));
        const float2 y01 = __half22float2(*reinterpret_cast<const __half2*>(&pb0.x));
        const float2 y23 = __half22float2(*reinterpret_cast<const __half2*>(&pb0.y));
        a0x += fmaxf(x01.x + y01.x + bb.x, 0.f);
        a0y += fmaxf(x01.y + y01.y + bb.y, 0.f);
        a0z += fmaxf(x23.x + y23.x + bb.z, 0.f);
        a0w += fmaxf(x23.y + y23.y + bb.w, 0.f);
    }
    for (; i1 + 2 <= s1b; i1 += 2) {
        const int2 e0 = __ldg(g_sab + i1);
        const int2 e1 = __ldg(g_sab + i1 + 1);
        const uint2 pa0 = *reinterpret_cast<const uint2*>(g_xwnh + (size_t)e0.x * 128 + lane * 4);
        const uint2 pb0 = *reinterpret_cast<const uint2*>(g_xwnh + (size_t)e0.y * 128 + lane * 4);
        const uint2 pa1 = *reinterpret_cast<const uint2*>(g_xwnh + (size_t)e1.x * 128 + lane * 4);
        const uint2 pb1 = *reinterpret_cast<const uint2*>(g_xwnh + (size_t)e1.y * 128 + lane * 4);
        {
            const float2 x01 = __half22float2(*reinterpret_cast<const __half2*>(&pa0.x));
            const float2 x23 = __half22float2(*reinterpret_cast<const __half2*>(&pa0.y));
            const float2 y01 = __half22float2(*reinterpret_cast<const __half2*>(&pb0.x));
            const float2 y23 = __half22float2(*reinterpret_cast<const __half2*>(&pb0.y));
            a1x += fmaxf(x01.x + y01.x + bb.x, 0.f);
            a1y += fmaxf(x01.y + y01.y + bb.y, 0.f);
            a1z += fmaxf(x23.x + y23.x + bb.z, 0.f);
            a1w += fmaxf(x23.y + y23.y + bb.w, 0.f);
        }
        {
            const float2 x01 = __half22float2(*reinterpret_cast<const __half2*>(&pa1.x));
            const float2 x23 = __half22float2(*reinterpret_cast<const __half2*>(&pa1.y));
            const float2 y01 = __half22float2(*reinterpret_cast<const __half2*>(&pb1.x));
            const float2 y23 = __half22float2(*reinterpret_cast<const __half2*>(&pb1.y));
            a1x += fmaxf(x01.x + y01.x + bb.x, 0.f);
            a1y += fmaxf(x01.y + y01.y + bb.y, 0.f);
            a1z += fmaxf(x23.x + y23.x + bb.z, 0.f);
            a1w += fmaxf(x23.y + y23.y + bb.w, 0.f);
        }
    }
    for (; i1 < s1b; i1++) {
        const int2 e0 = __ldg(g_sab + i1);
        const uint2 pa0 = *reinterpret_cast<const uint2*>(g_xwnh + (size_t)e0.x * 128 + lane * 4);
        const uint2 pb0 = *reinterpret_cast<const uint2*>(g_xwnh + (size_t)e0.y * 128 + lane * 4);
        const float2 x01 = __half22float2(*reinterpret_cast<const __half2*>(&pa0.x));
        const float2 x23 = __half22float2(*reinterpret_cast<const __half2*>(&pa0.y));
        const float2 y01 = __half22float2(*reinterpret_cast<const __half2*>(&pb0.x));
        const float2 y23 = __half22float2(*reinterpret_cast<const __half2*>(&pb0.y));
        a1x += fmaxf(x01.x + y01.x + bb.x, 0.f);
        a1y += fmaxf(x01.y + y01.y + bb.y, 0.f);
        a1z += fmaxf(x23.x + y23.x + bb.z, 0.f);
        a1w += fmaxf(x23.y + y23.y + bb.w, 0.f);
    }

    *reinterpret_cast<float4*>(g_conv + (size_t)r0 * 128 + lane * 4) =
        make_float4(a0x, a0y, a0z, a0w);
    if (r1 != r0)
        *reinterpret_cast<float4*>(g_conv + (size_t)r1 * 128 + lane * 4) =
            make_float4(a1x, a1y, a1z, a1w);
}

// ---------------------------------------------------------------------------
// Phase 4: fused final dual GEMM + epilogue over rows [r_lo, r_hi),
// 64-row chunks. 16 warps: m-group = wid&3, n-group = wid>>2 (full 128 cols).
// ---------------------------------------------------------------------------
#define FBL_OFF  0
#define FBF_OFF  TILE_BYTES
#define FA0_OFF  (2 * TILE_BYTES)
#define FA1_OFF  (2 * TILE_BYTES + FTILE_BYTES)
#define SMEM_F   (2 * TILE_BYTES + 2 * FTILE_BYTES)   // 104448 B

__global__ __launch_bounds__(512, 1)
void gemm_final_kernel(const float* __restrict__ b, float* __restrict__ out,
                       int r_lo, int r_hi) {
    extern __shared__ __align__(16) char smem[];
    const uint32_t sb = smem_u32(smem);

    const int tid = threadIdx.x;
    const int ntiles = (r_hi - r_lo + 63) / 64;
    const int stride = gridDim.x;
    const uint32_t aoff[2] = { FA0_OFF, FA1_OFF };

    load_b_tile(smem + FBL_OFF, g_wth + 0 * 16384, tid);
    load_b_tile(smem + FBF_OFF, g_wth + 1 * 16384, tid);

    int tile0 = blockIdx.x;
    if (tile0 < ntiles) {
#pragma unroll
        for (int j = 0; j < 2; j++) {
            const int i = tid + j * 512;          // 64 rows x 16 chunks = 1024
            const int r = i >> 4, c = i & 15;
            const int gr = r_lo + tile0 * 64 + r;
            if (gr < r_hi)
                cp_async16(sb + aoff[0] + (uint32_t)(r * HPITCH_B + c * 16),
                           g_xh + (size_t)gr * 128 + c * 8);
        }
    }
    cp_commit();

    const int wid = tid >> 5, lane = tid & 31;
    const int g = lane >> 2, t = lane & 3;
    const int m_base = (wid & 3) * 16;
    const int n_base = (wid >> 2) * 32;

    int buf = 0;
    for (int tile = tile0; tile < ntiles; tile += stride, buf ^= 1) {
        const int nxt = tile + stride;
        if (nxt < ntiles) {
#pragma unroll
            for (int j = 0; j < 2; j++) {
                const int i = tid + j * 512;
                const int r = i >> 4, c = i & 15;
                const int gr = r_lo + nxt * 64 + r;
                if (gr < r_hi)
                    cp_async16(sb + aoff[buf ^ 1] + (uint32_t)(r * HPITCH_B + c * 16),
                               g_xh + (size_t)gr * 128 + c * 8);
            }
        }
        cp_commit();
        cp_wait1();
        __syncthreads();

        float accl[4][4], accf[4][4];
#pragma unroll
        for (int nt = 0; nt < 4; nt++)
#pragma unroll
            for (int j = 0; j < 4; j++) { accl[nt][j] = 0.f; accf[nt][j] = 0.f; }

        const char* ar  = smem + aoff[buf] + (m_base + g) * HPITCH_B + 4 * t;
        const char* brl = smem + FBL_OFF + (n_base + g) * HPITCH_B + 4 * t;
        const char* brf = smem + FBF_OFF + (n_base + g) * HPITCH_B + 4 * t;

#pragma unroll
        for (int ks = 0; ks < 8; ks++) {
            const int kb = ks * 32;
            const uint32_t a0 = *reinterpret_cast<const uint32_t*>(ar + kb);
            const uint32_t a1 = *reinterpret_cast<const uint32_t*>(ar + 8 * HPITCH_B + kb);
            const uint32_t a2 = *reinterpret_cast<const uint32_t*>(ar + kb + 16);
            const uint32_t a3 = *reinterpret_cast<const uint32_t*>(ar + 8 * HPITCH_B + kb + 16);
#pragma unroll
            for (int nt = 0; nt < 4; nt++) {
                const uint32_t bl0 = *reinterpret_cast<const uint32_t*>(brl + nt * 8 * HPITCH_B + kb);
                const uint32_t bl1 = *reinterpret_cast<const uint32_t*>(brl + nt * 8 * HPITCH_B + kb + 16);
                mma_f16(accl[nt], a0, a1, a2, a3, bl0, bl1);
                const uint32_t bf0 = *reinterpret_cast<const uint32_t*>(brf + nt * 8 * HPITCH_B + kb);
                const uint32_t bf1 = *reinterpret_cast<const uint32_t*>(brf + nt * 8 * HPITCH_B + kb + 16);
                mma_f16(accf[nt], a0, a1, a2, a3, bf0, bf1);
            }
        }

        const int r0 = r_lo + tile * 64 + m_base + g;
        const int r1 = r0 + 8;
#pragma unroll
        for (int nt = 0; nt < 4; nt++) {
            const int col = n_base + nt * 8 + 2 * t;
            const float2 b2 = __ldg(reinterpret_cast<const float2*>(b + col));
            if (r0 < r_hi) {
                const float2 cv = *reinterpret_cast<const float2*>(g_conv + (size_t)r0 * 128 + col);
                float2 o;
                o.x = fmaxf(fmaf(accf[nt][0], cv.x, accl[nt][0]) + b2.x, 0.f);
                o.y = fmaxf(fmaf(accf[nt][1], cv.y, accl[nt][1]) + b2.y, 0.f);
                *reinterpret_cast<float2*>(out + (size_t)r0 * 128 + col) = o;
            }
            if (r1 < r_hi) {
                const float2 cv = *reinterpret_cast<const float2*>(g_conv + (size_t)r1 * 128 + col);
                float2 o;
                o.x = fmaxf(fmaf(accf[nt][2], cv.x, accl[nt][2]) + b2.x, 0.f);
                o.y = fmaxf(fmaf(accf[nt][3], cv.y, accl[nt][3]) + b2.y, 0.f);
                *reinterpret_cast<float2*>(out + (size_t)r1 * 128 + col) = o;
            }
        }
        __syncthreads();
    }
}

// ---------------------------------------------------------------------------
extern "C" void kernel_launch(void* const* d_in, const int* in_sizes, int n_in,
                              void* d_out, int out_size) {
    const float* X  = (const float*)d_in[0];
    const int*   ra = (const int*)d_in[1];
    const int*   rb = (const int*)d_in[2];
    const int*   br = (const int*)d_in[3];
    const float* Wl = (const float*)d_in[4];
    const float* Wf = (const float*)d_in[5];
    const float* Wn = (const float*)d_in[6];
    const float* b  = (const float*)d_in[7];
    const float* bn = (const float*)d_in[8];
    float* out = (float*)d_out;

    const int n = in_sizes[0] / 128;   // 200000
    const int m = in_sizes[1];         // 2000000
    const int h = ((n / 2 + 127) / 128) * 128;   // split point, multiple of 128

    static cudaStream_t s_side = nullptr;
    static cudaEvent_t ev_fork, ev_sort, ev_conv1, ev_conv2;
    static bool init_done = false;
    if (!init_done) {
        cudaFuncSetAttribute(gemm_xwn_kernel,
                             cudaFuncAttributeMaxDynamicSharedMemorySize, SMEM_X);
        cudaFuncSetAttribute(gemm_final_kernel,
                             cudaFuncAttributeMaxDynamicSharedMemorySize, SMEM_F);
        cudaStreamCreateWithFlags(&s_side, cudaStreamNonBlocking);
        cudaEventCreateWithFlags(&ev_fork, cudaEventDisableTiming);
        cudaEventCreateWithFlags(&ev_sort, cudaEventDisableTiming);
        cudaEventCreateWithFlags(&ev_conv1, cudaEventDisableTiming);
        cudaEventCreateWithFlags(&ev_conv2, cudaEventDisableTiming);
        init_done = true;
    }

    // Fork: counting sort on the side stream, concurrent with fp16 prep +
    // the xwn GEMM on the main (capture-origin) stream.
    cudaEventRecord(ev_fork, 0);
    cudaStreamWaitEvent(s_side, ev_fork, 0);

    hist_zero_kernel<<<(HPAD + 255) / 256, 256, 0, s_side>>>();
    hist_kernel<<<1024, 256, 0, s_side>>>(br, m);
    scan1_kernel<<<NBLK, 256, 0, s_side>>>();
    scan2_kernel<<<1, 256, 0, s_side>>>();
    scan3_kernel<<<(n + 256) / 256, 256, 0, s_side>>>(n, m);
    scatter_kernel<<<(m + 255) / 256, 256, 0, s_side>>>(ra, rb, br, m);
    cudaEventRecord(ev_sort, s_side);

    prep_w_kernel<<<3, 256>>>(Wl, Wf, Wn);
    prep_x_kernel<<<(n * 32 + 255) / 256, 256>>>(X, n * 32);
    gemm_xwn_kernel<<<148, 512, SMEM_X>>>(n);

    // conv first half on main (needs sort + xwn)
    cudaStreamWaitEvent(0, ev_sort, 0);
    conv_row_kernel<<<(h + 15) / 16, 256>>>(bn, 0, h);
    cudaEventRecord(ev_conv1, 0);

    // conv second half on the side stream, overlapping gemm_final[0,h)
    cudaStreamWaitEvent(s_side, ev_conv1, 0);
    conv_row_kernel<<<(n - h + 15) / 16, 256, 0, s_side>>>(bn, h, n);
    cudaEventRecord(ev_conv2, s_side);

    gemm_final_kernel<<<148, 512, SMEM_F>>>(b, out, 0, h);

    cudaStreamWaitEvent(0, ev_conv2, 0);
    gemm_final_kernel<<<148, 512, SMEM_F>>>(b, out, h, n);
}

// round 16
// speedup vs baseline: 1.0721x; 1.0721x over previous
#include <cuda_runtime.h>
#include <cuda_fp16.h>
#include <cstdint>
#include <cstddef>

// ---------------------------------------------------------------------------
// WL2 graph conv layer — fp16 mma.sync GEMMs + counting-sorted gather conv.
//   main : prep_w -> prep_x -> gemm_xwn -> conv_row -> gemm_final
//   side : hist_zero -> hist -> scans -> scatter (joined before conv_row)
// R16 = R14 (300us) + fp16 g_conv storage (the ONLY change; R15's split
// overlap reverted — falsified).
// ---------------------------------------------------------------------------

#define NMAX   200000
#define MEDGE  2000000
#define HPAD   200704              // 196 * 1024 (padded histogram length)
#define NBLK   196                 // scan blocks of 1024
#define MAXELEMS ((size_t)NMAX * 128)

__device__ __half g_xh[MAXELEMS];        // fp16 copy of X
__device__ __half g_xwnh[MAXELEMS];      // fp16 neighbor projection
__device__ __half g_convh[MAXELEMS];     // fp16 conv rows (written once)
__device__ __half g_wth[3 * 128 * 128];  // W^T (K-major), fp16

__device__ int  g_hist[HPAD];
__device__ int  g_rowscan[HPAD];
__device__ int  g_bsum[NBLK];
__device__ int  g_bsumoff[NBLK];
__device__ int  g_rowstart[NMAX + 1];
__device__ int  g_cursor[NMAX];
__device__ int2 g_sab[MEDGE];            // sorted (ref_a, ref_b) pairs

// ---------------- helpers ----------------
__device__ __forceinline__ uint32_t smem_u32(const void* p) {
    uint32_t a;
    asm("{ .reg .u64 t; cvta.to.shared.u64 t, %1; cvt.u32.u64 %0, t; }"
        : "=r"(a) : "l"(p));
    return a;
}

__device__ __forceinline__ void cp_async16(uint32_t dst, const void* src) {
    asm volatile("cp.async.ca.shared.global [%0], [%1], 16;"
                 :: "r"(dst), "l"(src) : "memory");
}
__device__ __forceinline__ void cp_commit() {
    asm volatile("cp.async.commit_group;" ::: "memory");
}
__device__ __forceinline__ void cp_wait1() {
    asm volatile("cp.async.wait_group 1;" ::: "memory");
}

// fp16 mma with fp32 accumulators: D = A(16x16,row) * B(16x8,col) + D
__device__ __forceinline__ void mma_f16(float* c,
                                        uint32_t a0, uint32_t a1, uint32_t a2, uint32_t a3,
                                        uint32_t b0, uint32_t b1) {
    asm volatile(
        "mma.sync.aligned.m16n8k16.row.col.f32.f16.f16.f32 "
        "{%0,%1,%2,%3}, {%4,%5,%6,%7}, {%8,%9}, {%0,%1,%2,%3};"
        : "+f"(c[0]), "+f"(c[1]), "+f"(c[2]), "+f"(c[3])
        : "r"(a0), "r"(a1), "r"(a2), "r"(a3), "r"(b0), "r"(b1));
}

// smem tile geometry: rows of 128 halves padded to 136 (272 B).
#define HPITCH_B    272                   // bytes per padded row
#define TILE_BYTES  (128 * HPITCH_B)      // 34816 B per 128-row tile
#define FTILE_BYTES (64 * HPITCH_B)       // 17408 B per 64-row A tile

// ---------------------------------------------------------------------------
// Phase 0a: W^T -> fp16
// ---------------------------------------------------------------------------
__global__ void prep_w_kernel(const float* __restrict__ Wl,
                              const float* __restrict__ Wf,
                              const float* __restrict__ Wn) {
    const float* src = (blockIdx.x == 0) ? Wl : ((blockIdx.x == 1) ? Wf : Wn);
    __half* dst = g_wth + blockIdx.x * 16384;
    for (int i = threadIdx.x; i < 16384; i += blockDim.x) {
        int n = i >> 7, k = i & 127;
        dst[i] = __float2half_rn(src[k * 128 + n]);   // [n][k]
    }
}

// ---------------------------------------------------------------------------
// Phase 0b: X -> fp16
// ---------------------------------------------------------------------------
__global__ void prep_x_kernel(const float* __restrict__ X, int total4) {
    const int i = blockIdx.x * 256 + threadIdx.x;
    if (i >= total4) return;
    const float4 v = reinterpret_cast<const float4*>(X)[i];
    const __half2 h0 = __floats2half2_rn(v.x, v.y);
    const __half2 h1 = __floats2half2_rn(v.z, v.w);
    uint2 o;
    o.x = *reinterpret_cast<const uint32_t*>(&h0);
    o.y = *reinterpret_cast<const uint32_t*>(&h1);
    reinterpret_cast<uint2*>(g_xh)[i] = o;
}

// ---------------------------------------------------------------------------
// Phase 1 (side stream): counting sort of edges by backref
// ---------------------------------------------------------------------------
__global__ void hist_zero_kernel() {
    int i = blockIdx.x * 256 + threadIdx.x;
    if (i < HPAD) g_hist[i] = 0;
}

__global__ void hist_kernel(const int* __restrict__ br, int m) {
    for (int e = blockIdx.x * 256 + threadIdx.x; e < m; e += gridDim.x * 256)
        atomicAdd(&g_hist[__ldg(br + e)], 1);
}

__global__ void scan1_kernel() {
    __shared__ int wsum[8];
    const int t = threadIdx.x;
    const int base = blockIdx.x * 1024 + t * 4;
    const int4 v = *reinterpret_cast<const int4*>(g_hist + base);
    const int s1 = v.x + v.y, s2 = s1 + v.z, s3 = s2 + v.w;
    const int lane = t & 31, w = t >> 5;
    int x = s3;
#pragma unroll
    for (int d = 1; d < 32; d <<= 1) {
        int y = __shfl_up_sync(0xffffffffu, x, d);
        if (lane >= d) x += y;
    }
    if (lane == 31) wsum[w] = x;
    __syncthreads();
    if (t < 8) {
        int v2 = wsum[t];
#pragma unroll
        for (int d = 1; d < 8; d <<= 1) {
            int y = __shfl_up_sync(0xffu, v2, d);
            if (t >= d) v2 += y;
        }
        wsum[t] = v2;
    }
    __syncthreads();
    const int woff = w ? wsum[w - 1] : 0;
    const int excl = woff + x - s3;
    int4 o;
    o.x = excl; o.y = excl + v.x; o.z = excl + s1; o.w = excl + s2;
    *reinterpret_cast<int4*>(g_rowscan + base) = o;
    if (t == 255) g_bsum[blockIdx.x] = wsum[7];
}

__global__ void scan2_kernel() {
    __shared__ int wsum[8];
    const int t = threadIdx.x;
    const int v = (t < NBLK) ? g_bsum[t] : 0;
    const int lane = t & 31, w = t >> 5;
    int x = v;
#pragma unroll
    for (int d = 1; d < 32; d <<= 1) {
        int y = __shfl_up_sync(0xffffffffu, x, d);
        if (lane >= d) x += y;
    }
    if (lane == 31) wsum[w] = x;
    __syncthreads();
    if (t < 8) {
        int v2 = wsum[t];
#pragma unroll
        for (int d = 1; d < 8; d <<= 1) {
            int y = __shfl_up_sync(0xffu, v2, d);
            if (t >= d) v2 += y;
        }
        wsum[t] = v2;
    }
    __syncthreads();
    const int woff = w ? wsum[w - 1] : 0;
    if (t < NBLK) g_bsumoff[t] = woff + x - v;
}

__global__ void scan3_kernel(int n, int m) {
    const int i = blockIdx.x * 256 + threadIdx.x;
    if (i < n) {
        const int val = g_rowscan[i] + g_bsumoff[i >> 10];
        g_rowstart[i] = val;
        g_cursor[i] = val;
    }
    if (i == 0) g_rowstart[n] = m;
}

__global__ void scatter_kernel(const int* __restrict__ ra,
                               const int* __restrict__ rb,
                               const int* __restrict__ br, int m) {
    const int e = blockIdx.x * 256 + threadIdx.x;
    if (e >= m) return;
    const int c = __ldg(br + e);
    const int p = atomicAdd(&g_cursor[c], 1);
    g_sab[p] = make_int2(__ldg(ra + e), __ldg(rb + e));
}

// ---------------------------------------------------------------------------
// B-tile loader: g_wth [n][k] fp16 -> smem padded rows. 512 threads.
// ---------------------------------------------------------------------------
__device__ __forceinline__ void load_b_tile(char* dst, const __half* __restrict__ Wt,
                                            int tid) {
    for (int i = tid; i < 2048; i += 512) {
        const int r = i >> 4, c = i & 15;
        const uint4 v = *reinterpret_cast<const uint4*>(Wt + r * 128 + c * 8);
        *reinterpret_cast<uint4*>(dst + r * HPITCH_B + c * 16) = v;
    }
}

// ---------------------------------------------------------------------------
// Phase 2: XW_n = X @ W_n, persistent; 128-row chunks, double-buffered A.
// 16 warps: m-group = wid&7 (16 rows), n-group = wid>>3 (64 cols, 8 nt).
// ---------------------------------------------------------------------------
#define XB_OFF   0
#define XA0_OFF  TILE_BYTES
#define XA1_OFF  (2 * TILE_BYTES)
#define SMEM_X   (3 * TILE_BYTES)      // 104448 B

__global__ __launch_bounds__(512, 1)
void gemm_xwn_kernel(int nrows) {
    extern __shared__ __align__(16) char smem[];
    const uint32_t sb = smem_u32(smem);

    const int tid = threadIdx.x;
    const int ntiles = (nrows + 127) / 128;
    const int stride = gridDim.x;
    const uint32_t aoff[2] = { XA0_OFF, XA1_OFF };

    load_b_tile(smem + XB_OFF, g_wth + 2 * 16384, tid);

    int tile0 = blockIdx.x;
    if (tile0 < ntiles) {
#pragma unroll
        for (int j = 0; j < 4; j++) {
            const int i = tid + j * 512;
            const int r = i >> 4, c = i & 15;
            const int gr = tile0 * 128 + r;
            if (gr < nrows)
                cp_async16(sb + aoff[0] + (uint32_t)(r * HPITCH_B + c * 16),
                           g_xh + (size_t)gr * 128 + c * 8);
        }
    }
    cp_commit();

    const int wid = tid >> 5, lane = tid & 31;
    const int g = lane >> 2, t = lane & 3;
    const int m_base = (wid & 7) * 16;
    const int n_base = (wid >> 3) * 64;

    int buf = 0;
    for (int tile = tile0; tile < ntiles; tile += stride, buf ^= 1) {
        const int nxt = tile + stride;
        if (nxt < ntiles) {
#pragma unroll
            for (int j = 0; j < 4; j++) {
                const int i = tid + j * 512;
                const int r = i >> 4, c = i & 15;
                const int gr = nxt * 128 + r;
                if (gr < nrows)
                    cp_async16(sb + aoff[buf ^ 1] + (uint32_t)(r * HPITCH_B + c * 16),
                               g_xh + (size_t)gr * 128 + c * 8);
            }
        }
        cp_commit();
        cp_wait1();
        __syncthreads();

        float acc[8][4];
#pragma unroll
        for (int nt = 0; nt < 8; nt++)
#pragma unroll
            for (int j = 0; j < 4; j++) acc[nt][j] = 0.f;

        const char* ar = smem + aoff[buf] + (m_base + g) * HPITCH_B + 4 * t;
        const char* br = smem + XB_OFF + (n_base + g) * HPITCH_B + 4 * t;

#pragma unroll
        for (int ks = 0; ks < 8; ks++) {
            const int kb = ks * 32;   // 16 halves = 32 bytes per K-step
            const uint32_t a0 = *reinterpret_cast<const uint32_t*>(ar + kb);
            const uint32_t a1 = *reinterpret_cast<const uint32_t*>(ar + 8 * HPITCH_B + kb);
            const uint32_t a2 = *reinterpret_cast<const uint32_t*>(ar + kb + 16);
            const uint32_t a3 = *reinterpret_cast<const uint32_t*>(ar + 8 * HPITCH_B + kb + 16);
#pragma unroll
            for (int nt = 0; nt < 8; nt++) {
                const uint32_t b0 = *reinterpret_cast<const uint32_t*>(br + nt * 8 * HPITCH_B + kb);
                const uint32_t b1 = *reinterpret_cast<const uint32_t*>(br + nt * 8 * HPITCH_B + kb + 16);
                mma_f16(acc[nt], a0, a1, a2, a3, b0, b1);
            }
        }

        const int r0 = tile * 128 + m_base + g;
        const int r1 = r0 + 8;
#pragma unroll
        for (int nt = 0; nt < 8; nt++) {
            const int col = n_base + nt * 8 + 2 * t;
            if (r0 < nrows)
                *reinterpret_cast<__half2*>(g_xwnh + (size_t)r0 * 128 + col) =
                    __floats2half2_rn(acc[nt][0], acc[nt][1]);
            if (r1 < nrows)
                *reinterpret_cast<__half2*>(g_xwnh + (size_t)r1 * 128 + col) =
                    __floats2half2_rn(acc[nt][2], acc[nt][3]);
        }
        __syncthreads();
    }
}

// ---------------------------------------------------------------------------
// Phase 3: conv rows. One warp per TWO rows (interleaved gathers for MLP);
// register sum, single coalesced fp16 store per row.
// ---------------------------------------------------------------------------
__global__ __launch_bounds__(256)
void conv_row_kernel(const float* __restrict__ bn, int n) {
    const int wid = threadIdx.x >> 5, lane = threadIdx.x & 31;
    const int r0 = (blockIdx.x * 8 + wid) * 2;
    if (r0 >= n) return;
    const int r1 = (r0 + 1 < n) ? (r0 + 1) : r0;

    const int s0a = g_rowstart[r0];
    const int s0b = g_rowstart[r0 + 1];
    const int s1a = (r1 != r0) ? g_rowstart[r1] : s0a;
    const int s1b = (r1 != r0) ? g_rowstart[r1 + 1] : s0a;

    const float4 bb = __ldg(reinterpret_cast<const float4*>(bn) + lane);

    float a0x = 0.f, a0y = 0.f, a0z = 0.f, a0w = 0.f;
    float a1x = 0.f, a1y = 0.f, a1z = 0.f, a1w = 0.f;

    int i0 = s0a, i1 = s1a;
    while (i0 < s0b && i1 < s1b) {
        const int2 e0 = __ldg(g_sab + i0);
        const int2 e1 = __ldg(g_sab + i1);
        const uint2 pa0 = *reinterpret_cast<const uint2*>(g_xwnh + (size_t)e0.x * 128 + lane * 4);
        const uint2 pb0 = *reinterpret_cast<const uint2*>(g_xwnh + (size_t)e0.y * 128 + lane * 4);
        const uint2 pa1 = *reinterpret_cast<const uint2*>(g_xwnh + (size_t)e1.x * 128 + lane * 4);
        const uint2 pb1 = *reinterpret_cast<const uint2*>(g_xwnh + (size_t)e1.y * 128 + lane * 4);
        {
            const float2 x01 = __half22float2(*reinterpret_cast<const __half2*>(&pa0.x));
            const float2 x23 = __half22float2(*reinterpret_cast<const __half2*>(&pa0.y));
            const float2 y01 = __half22float2(*reinterpret_cast<const __half2*>(&pb0.x));
            const float2 y23 = __half22float2(*reinterpret_cast<const __half2*>(&pb0.y));
            a0x += fmaxf(x01.x + y01.x + bb.x, 0.f);
            a0y += fmaxf(x01.y + y01.y + bb.y, 0.f);
            a0z += fmaxf(x23.x + y23.x + bb.z, 0.f);
            a0w += fmaxf(x23.y + y23.y + bb.w, 0.f);
        }
        {
            const float2 x01 = __half22float2(*reinterpret_cast<const __half2*>(&pa1.x));
            const float2 x23 = __half22float2(*reinterpret_cast<const __half2*>(&pa1.y));
            const float2 y01 = __half22float2(*reinterpret_cast<const __half2*>(&pb1.x));
            const float2 y23 = __half22float2(*reinterpret_cast<const __half2*>(&pb1.y));
            a1x += fmaxf(x01.x + y01.x + bb.x, 0.f);
            a1y += fmaxf(x01.y + y01.y + bb.y, 0.f);
            a1z += fmaxf(x23.x + y23.x + bb.z, 0.f);
            a1w += fmaxf(x23.y + y23.y + bb.w, 0.f);
        }
        i0++; i1++;
    }
    for (; i0 + 2 <= s0b; i0 += 2) {
        const int2 e0 = __ldg(g_sab + i0);
        const int2 e1 = __ldg(g_sab + i0 + 1);
        const uint2 pa0 = *reinterpret_cast<const uint2*>(g_xwnh + (size_t)e0.x * 128 + lane * 4);
        const uint2 pb0 = *reinterpret_cast<const uint2*>(g_xwnh + (size_t)e0.y * 128 + lane * 4);
        const uint2 pa1 = *reinterpret_cast<const uint2*>(g_xwnh + (size_t)e1.x * 128 + lane * 4);
        const uint2 pb1 = *reinterpret_cast<const uint2*>(g_xwnh + (size_t)e1.y * 128 + lane * 4);
        {
            const float2 x01 = __half22float2(*reinterpret_cast<const __half2*>(&pa0.x));
            const float2 x23 = __half22float2(*reinterpret_cast<const __half2*>(&pa0.y));
            const float2 y01 = __half22float2(*reinterpret_cast<const __half2*>(&pb0.x));
            const float2 y23 = __half22float2(*reinterpret_cast<const __half2*>(&pb0.y));
            a0x += fmaxf(x01.x + y01.x + bb.x, 0.f);
            a0y += fmaxf(x01.y + y01.y + bb.y, 0.f);
            a0z += fmaxf(x23.x + y23.x + bb.z, 0.f);
            a0w += fmaxf(x23.y + y23.y + bb.w, 0.f);
        }
        {
            const float2 x01 = __half22float2(*reinterpret_cast<const __half2*>(&pa1.x));
            const float2 x23 = __half22float2(*reinterpret_cast<const __half2*>(&pa1.y));
            const float2 y01 = __half22float2(*reinterpret_cast<const __half2*>(&pb1.x));
            const float2 y23 = __half22float2(*reinterpret_cast<const __half2*>(&pb1.y));
            a0x += fmaxf(x01.x + y01.x + bb.x, 0.f);
            a0y += fmaxf(x01.y + y01.y + bb.y, 0.f);
            a0z += fmaxf(x23.x + y23.x + bb.z, 0.f);
            a0w += fmaxf(x23.y + y23.y + bb.w, 0.f);
        }
    }
    for (; i0 < s0b; i0++) {
        const int2 e0 = __ldg(g_sab + i0);
        const uint2 pa0 = *reinterpret_cast<const uint2*>(g_xwnh + (size_t)e0.x * 128 + lane * 4);
        const uint2 pb0 = *reinterpret_cast<const uint2*>(g_xwnh + (size_t)e0.y * 128 + lane * 4);
        const float2 x01 = __half22float2(*reinterpret_cast<const __half2*>(&pa0.x));
        const float2 x23 = __half22float2(*reinterpret_cast<const __half2*>(&pa0.y));
        const float2 y01 = __half22float2(*reinterpret_cast<const __half2*>(&pb0.x));
        const float2 y23 = __half22float2(*reinterpret_cast<const __half2*>(&pb0.y));
        a0x += fmaxf(x01.x + y01.x + bb.x, 0.f);
        a0y += fmaxf(x01.y + y01.y + bb.y, 0.f);
        a0z += fmaxf(x23.x + y23.x + bb.z, 0.f);
        a0w += fmaxf(x23.y + y23.y + bb.w, 0.f);
    }
    for (; i1 + 2 <= s1b; i1 += 2) {
        const int2 e0 = __ldg(g_sab + i1);
        const int2 e1 = __ldg(g_sab + i1 + 1);
        const uint2 pa0 = *reinterpret_cast<const uint2*>(g_xwnh + (size_t)e0.x * 128 + lane * 4);
        const uint2 pb0 = *reinterpret_cast<const uint2*>(g_xwnh + (size_t)e0.y * 128 + lane * 4);
        const uint2 pa1 = *reinterpret_cast<const uint2*>(g_xwnh + (size_t)e1.x * 128 + lane * 4);
        const uint2 pb1 = *reinterpret_cast<const uint2*>(g_xwnh + (size_t)e1.y * 128 + lane * 4);
        {
            const float2 x01 = __half22float2(*reinterpret_cast<const __half2*>(&pa0.x));
            const float2 x23 = __half22float2(*reinterpret_cast<const __half2*>(&pa0.y));
            const float2 y01 = __half22float2(*reinterpret_cast<const __half2*>(&pb0.x));
            const float2 y23 = __half22float2(*reinterpret_cast<const __half2*>(&pb0.y));
            a1x += fmaxf(x01.x + y01.x + bb.x, 0.f);
            a1y += fmaxf(x01.y + y01.y + bb.y, 0.f);
            a1z += fmaxf(x23.x + y23.x + bb.z, 0.f);
            a1w += fmaxf(x23.y + y23.y + bb.w, 0.f);
        }
        {
            const float2 x01 = __half22float2(*reinterpret_cast<const __half2*>(&pa1.x));
            const float2 x23 = __half22float2(*reinterpret_cast<const __half2*>(&pa1.y));
            const float2 y01 = __half22float2(*reinterpret_cast<const __half2*>(&pb1.x));
            const float2 y23 = __half22float2(*reinterpret_cast<const __half2*>(&pb1.y));
            a1x += fmaxf(x01.x + y01.x + bb.x, 0.f);
            a1y += fmaxf(x01.y + y01.y + bb.y, 0.f);
            a1z += fmaxf(x23.x + y23.x + bb.z, 0.f);
            a1w += fmaxf(x23.y + y23.y + bb.w, 0.f);
        }
    }
    for (; i1 < s1b; i1++) {
        const int2 e0 = __ldg(g_sab + i1);
        const uint2 pa0 = *reinterpret_cast<const uint2*>(g_xwnh + (size_t)e0.x * 128 + lane * 4);
        const uint2 pb0 = *reinterpret_cast<const uint2*>(g_xwnh + (size_t)e0.y * 128 + lane * 4);
        const float2 x01 = __half22float2(*reinterpret_cast<const __half2*>(&pa0.x));
        const float2 x23 = __half22float2(*reinterpret_cast<const __half2*>(&pa0.y));
        const float2 y01 = __half22float2(*reinterpret_cast<const __half2*>(&pb0.x));
        const float2 y23 = __half22float2(*reinterpret_cast<const __half2*>(&pb0.y));
        a1x += fmaxf(x01.x + y01.x + bb.x, 0.f);
        a1y += fmaxf(x01.y + y01.y + bb.y, 0.f);
        a1z += fmaxf(x23.x + y23.x + bb.z, 0.f);
        a1w += fmaxf(x23.y + y23.y + bb.w, 0.f);
    }

    {
        const __half2 h0 = __floats2half2_rn(a0x, a0y);
        const __half2 h1 = __floats2half2_rn(a0z, a0w);
        uint2 o;
        o.x = *reinterpret_cast<const uint32_t*>(&h0);
        o.y = *reinterpret_cast<const uint32_t*>(&h1);
        *reinterpret_cast<uint2*>(g_convh + (size_t)r0 * 128 + lane * 4) = o;
    }
    if (r1 != r0) {
        const __half2 h0 = __floats2half2_rn(a1x, a1y);
        const __half2 h1 = __floats2half2_rn(a1z, a1w);
        uint2 o;
        o.x = *reinterpret_cast<const uint32_t*>(&h0);
        o.y = *reinterpret_cast<const uint32_t*>(&h1);
        *reinterpret_cast<uint2*>(g_convh + (size_t)r1 * 128 + lane * 4) = o;
    }
}

// ---------------------------------------------------------------------------
// Phase 4: fused final dual GEMM + epilogue, 64-row chunks.
// 16 warps: m-group = wid&3 (4x16 = 64 rows), n-group = wid>>2 (4x32 = 128
// cols, 4 nt per warp per W matrix). Conv read as fp16.
// ---------------------------------------------------------------------------
#define FBL_OFF  0
#define FBF_OFF  TILE_BYTES
#define FA0_OFF  (2 * TILE_BYTES)
#define FA1_OFF  (2 * TILE_BYTES + FTILE_BYTES)
#define SMEM_F   (2 * TILE_BYTES + 2 * FTILE_BYTES)   // 104448 B

__global__ __launch_bounds__(512, 1)
void gemm_final_kernel(const float* __restrict__ b, float* __restrict__ out,
                       int nrows) {
    extern __shared__ __align__(16) char smem[];
    const uint32_t sb = smem_u32(smem);

    const int tid = threadIdx.x;
    const int ntiles = (nrows + 63) / 64;
    const int stride = gridDim.x;
    const uint32_t aoff[2] = { FA0_OFF, FA1_OFF };

    load_b_tile(smem + FBL_OFF, g_wth + 0 * 16384, tid);
    load_b_tile(smem + FBF_OFF, g_wth + 1 * 16384, tid);

    int tile0 = blockIdx.x;
    if (tile0 < ntiles) {
#pragma unroll
        for (int j = 0; j < 2; j++) {
            const int i = tid + j * 512;          // 64 rows x 16 chunks = 1024
            const int r = i >> 4, c = i & 15;
            const int gr = tile0 * 64 + r;
            if (gr < nrows)
                cp_async16(sb + aoff[0] + (uint32_t)(r * HPITCH_B + c * 16),
                           g_xh + (size_t)gr * 128 + c * 8);
        }
    }
    cp_commit();

    const int wid = tid >> 5, lane = tid & 31;
    const int g = lane >> 2, t = lane & 3;
    const int m_base = (wid & 3) * 16;
    const int n_base = (wid >> 2) * 32;

    int buf = 0;
    for (int tile = tile0; tile < ntiles; tile += stride, buf ^= 1) {
        const int nxt = tile + stride;
        if (nxt < ntiles) {
#pragma unroll
            for (int j = 0; j < 2; j++) {
                const int i = tid + j * 512;
                const int r = i >> 4, c = i & 15;
                const int gr = nxt * 64 + r;
                if (gr < nrows)
                    cp_async16(sb + aoff[buf ^ 1] + (uint32_t)(r * HPITCH_B + c * 16),
                               g_xh + (size_t)gr * 128 + c * 8);
            }
        }
        cp_commit();
        cp_wait1();
        __syncthreads();

        float accl[4][4], accf[4][4];
#pragma unroll
        for (int nt = 0; nt < 4; nt++)
#pragma unroll
            for (int j = 0; j < 4; j++) { accl[nt][j] = 0.f; accf[nt][j] = 0.f; }

        const char* ar  = smem + aoff[buf] + (m_base + g) * HPITCH_B + 4 * t;
        const char* brl = smem + FBL_OFF + (n_base + g) * HPITCH_B + 4 * t;
        const char* brf = smem + FBF_OFF + (n_base + g) * HPITCH_B + 4 * t;

#pragma unroll
        for (int ks = 0; ks < 8; ks++) {
            const int kb = ks * 32;
            const uint32_t a0 = *reinterpret_cast<const uint32_t*>(ar + kb);
            const uint32_t a1 = *reinterpret_cast<const uint32_t*>(ar + 8 * HPITCH_B + kb);
            const uint32_t a2 = *reinterpret_cast<const uint32_t*>(ar + kb + 16);
            const uint32_t a3 = *reinterpret_cast<const uint32_t*>(ar + 8 * HPITCH_B + kb + 16);
#pragma unroll
            for (int nt = 0; nt < 4; nt++) {
                const uint32_t bl0 = *reinterpret_cast<const uint32_t*>(brl + nt * 8 * HPITCH_B + kb);
                const uint32_t bl1 = *reinterpret_cast<const uint32_t*>(brl + nt * 8 * HPITCH_B + kb + 16);
                mma_f16(accl[nt], a0, a1, a2, a3, bl0, bl1);
                const uint32_t bf0 = *reinterpret_cast<const uint32_t*>(brf + nt * 8 * HPITCH_B + kb);
                const uint32_t bf1 = *reinterpret_cast<const uint32_t*>(brf + nt * 8 * HPITCH_B + kb + 16);
                mma_f16(accf[nt], a0, a1, a2, a3, bf0, bf1);
            }
        }

        const int r0 = tile * 64 + m_base + g;
        const int r1 = r0 + 8;
#pragma unroll
        for (int nt = 0; nt < 4; nt++) {
            const int col = n_base + nt * 8 + 2 * t;
            const float2 b2 = __ldg(reinterpret_cast<const float2*>(b + col));
            if (r0 < nrows) {
                const float2 cv = __half22float2(
                    *reinterpret_cast<const __half2*>(g_convh + (size_t)r0 * 128 + col));
                float2 o;
                o.x = fmaxf(fmaf(accf[nt][0], cv.x, accl[nt][0]) + b2.x, 0.f);
                o.y = fmaxf(fmaf(accf[nt][1], cv.y, accl[nt][1]) + b2.y, 0.f);
                *reinterpret_cast<float2*>(out + (size_t)r0 * 128 + col) = o;
            }
            if (r1 < nrows) {
                const float2 cv = __half22float2(
                    *reinterpret_cast<const __half2*>(g_convh + (size_t)r1 * 128 + col));
                float2 o;
                o.x = fmaxf(fmaf(accf[nt][2], cv.x, accl[nt][2]) + b2.x, 0.f);
                o.y = fmaxf(fmaf(accf[nt][3], cv.y, accl[nt][3]) + b2.y, 0.f);
                *reinterpret_cast<float2*>(out + (size_t)r1 * 128 + col) = o;
            }
        }
        __syncthreads();
    }
}

// ---------------------------------------------------------------------------
extern "C" void kernel_launch(void* const* d_in, const int* in_sizes, int n_in,
                              void* d_out, int out_size) {
    const float* X  = (const float*)d_in[0];
    const int*   ra = (const int*)d_in[1];
    const int*   rb = (const int*)d_in[2];
    const int*   br = (const int*)d_in[3];
    const float* Wl = (const float*)d_in[4];
    const float* Wf = (const float*)d_in[5];
    const float* Wn = (const float*)d_in[6];
    const float* b  = (const float*)d_in[7];
    const float* bn = (const float*)d_in[8];
    float* out = (float*)d_out;

    const int n = in_sizes[0] / 128;   // 200000
    const int m = in_sizes[1];         // 2000000

    static cudaStream_t s_side = nullptr;
    static cudaEvent_t ev_fork, ev_join;
    static bool init_done = false;
    if (!init_done) {
        cudaFuncSetAttribute(gemm_xwn_kernel,
                             cudaFuncAttributeMaxDynamicSharedMemorySize, SMEM_X);
        cudaFuncSetAttribute(gemm_final_kernel,
                             cudaFuncAttributeMaxDynamicSharedMemorySize, SMEM_F);
        cudaStreamCreateWithFlags(&s_side, cudaStreamNonBlocking);
        cudaEventCreateWithFlags(&ev_fork, cudaEventDisableTiming);
        cudaEventCreateWithFlags(&ev_join, cudaEventDisableTiming);
        init_done = true;
    }

    // Fork: counting sort on the side stream, concurrent with fp16 prep +
    // the xwn GEMM on the main (capture-origin) stream.
    cudaEventRecord(ev_fork, 0);
    cudaStreamWaitEvent(s_side, ev_fork, 0);

    hist_zero_kernel<<<(HPAD + 255) / 256, 256, 0, s_side>>>();
    hist_kernel<<<1024, 256, 0, s_side>>>(br, m);
    scan1_kernel<<<NBLK, 256, 0, s_side>>>();
    scan2_kernel<<<1, 256, 0, s_side>>>();
    scan3_kernel<<<(n + 256) / 256, 256, 0, s_side>>>(n, m);
    scatter_kernel<<<(m + 255) / 256, 256, 0, s_side>>>(ra, rb, br, m);
    cudaEventRecord(ev_join, s_side);

    prep_w_kernel<<<3, 256>>>(Wl, Wf, Wn);
    prep_x_kernel<<<(n * 32 + 255) / 256, 256>>>(X, n * 32);
    gemm_xwn_kernel<<<148, 512, SMEM_X>>>(n);

    // Join: conv needs both the sorted edges and the xwn projection.
    cudaStreamWaitEvent(0, ev_join, 0);
    conv_row_kernel<<<(n + 15) / 16, 256>>>(bn, n);
    gemm_final_kernel<<<148, 512, SMEM_F>>>(b, out, n);
}